// round 6
// baseline (speedup 1.0000x reference)
#include <cuda_runtime.h>
#include <stdint.h>

// QLinearLayerSign via int8 mma.sync (exact):
//   A[m,k] = (x>0) ? 1 : 0   (s8)
//   B[n,k] = (W>0) ? 1 : -1  (s8)
//   out[m,n] = (float) sum_k A*B   (s32 accum, |acc| <= 4096, exact)

#define BATCH 8192
#define INF   4096
#define OUTF  4096

#define BM 128
#define BN 256
#define BK 64                    // int8 elems (bytes) per k-chunk
#define KCHUNKS (INF / BK)       // 64
#define STRIDE 80                // padded smem row stride (conflict-free)

#define SM_A_OFF  0
#define SM_A_SZ   (BM * STRIDE)              // 10240
#define SM_B_OFF  SM_A_SZ
#define SM_B_SZ   (BN * STRIDE)              // 20480
#define SM_STAGE  (SM_A_SZ + SM_B_SZ)        // 30720
#define SM_TOTAL  (2 * SM_STAGE)             // 61440

__device__ int8_t g_X8[(size_t)BATCH * INF];   // 32 MB
__device__ int8_t g_W8[(size_t)OUTF * INF];    // 16 MB

__device__ __forceinline__ uint32_t smem_u32(const void* p) {
    uint32_t a;
    asm("{ .reg .u64 t; cvta.to.shared.u64 t, %1; cvt.u32.u64 %0, t; }" : "=r"(a) : "l"(p));
    return a;
}
__device__ __forceinline__ void cp16(uint32_t dst, const void* src) {
    asm volatile("cp.async.cg.shared.global [%0], [%1], 16;" :: "r"(dst), "l"(src));
}
__device__ __forceinline__ void cp_commit() {
    asm volatile("cp.async.commit_group;" ::: "memory");
}
__device__ __forceinline__ void cp_wait1() {
    asm volatile("cp.async.wait_group 1;" ::: "memory");
}
__device__ __forceinline__ void cp_wait0() {
    asm volatile("cp.async.wait_group 0;" ::: "memory");
}
__device__ __forceinline__ void imma(int* d, const uint32_t* a, const uint32_t* b) {
    asm volatile(
        "mma.sync.aligned.m16n8k32.row.col.s32.s8.s8.s32 "
        "{%0,%1,%2,%3}, {%4,%5,%6,%7}, {%8,%9}, {%0,%1,%2,%3};"
        : "+r"(d[0]), "+r"(d[1]), "+r"(d[2]), "+r"(d[3])
        : "r"(a[0]), "r"(a[1]), "r"(a[2]), "r"(a[3]), "r"(b[0]), "r"(b[1]));
}

// ---------------------------------------------------------------------------
// Conversion: fp32 -> s8. 16 elems per thread, uint4 packed-byte stores.
// ---------------------------------------------------------------------------
__global__ __launch_bounds__(256) void conv_x8_kernel(const float* __restrict__ x,
                                                      int8_t* __restrict__ d) {
    size_t base = ((size_t)blockIdx.x * 256 + threadIdx.x) * 16;
    uint32_t w[4];
    #pragma unroll
    for (int i = 0; i < 4; ++i) {
        float4 f = *reinterpret_cast<const float4*>(x + base + i * 4);
        w[i] = (f.x > 0.f ? 1u : 0u) | ((f.y > 0.f ? 1u : 0u) << 8) |
               ((f.z > 0.f ? 1u : 0u) << 16) | ((f.w > 0.f ? 1u : 0u) << 24);
    }
    *reinterpret_cast<uint4*>(d + base) = make_uint4(w[0], w[1], w[2], w[3]);
}
__global__ __launch_bounds__(256) void conv_w8_kernel(const float* __restrict__ x,
                                                      int8_t* __restrict__ d) {
    size_t base = ((size_t)blockIdx.x * 256 + threadIdx.x) * 16;
    uint32_t w[4];
    #pragma unroll
    for (int i = 0; i < 4; ++i) {
        float4 f = *reinterpret_cast<const float4*>(x + base + i * 4);
        w[i] = (f.x > 0.f ? 1u : 0xFFu) | ((f.y > 0.f ? 1u : 0xFFu) << 8) |
               ((f.z > 0.f ? 1u : 0xFFu) << 16) | ((f.w > 0.f ? 1u : 0xFFu) << 24);
    }
    *reinterpret_cast<uint4*>(d + base) = make_uint4(w[0], w[1], w[2], w[3]);
}

// ---------------------------------------------------------------------------
// Int8 IMMA GEMM: out[M,N] = A[M,K] @ B[N,K]^T.
// CTA 128x256, 8 warps, warp tile 64x64 (4 m-tiles x 8 n-tiles of m16n8k32).
// 2-stage cp.async pipeline over BK=64 chunks.
// ---------------------------------------------------------------------------
__global__ __launch_bounds__(256, 1)
void bgemm_imma_kernel(const int8_t* __restrict__ A,
                       const int8_t* __restrict__ B,
                       float* __restrict__ out)
{
    extern __shared__ char smem[];
    const uint32_t sb = smem_u32(smem);
    const int tid = threadIdx.x;
    const int m0 = blockIdx.y * BM;
    const int n0 = blockIdx.x * BN;

    const int w    = tid >> 5;
    const int lane = tid & 31;
    const int rg   = lane >> 2;      // group id (row within 8)
    const int tg   = lane & 3;       // thread in group
    const int wm   = w >> 2;         // 0..1 -> m offset 64*wm
    const int wn   = w & 3;          // 0..3 -> n offset 64*wn

    int acc[4][8][4];
    #pragma unroll
    for (int mt = 0; mt < 4; ++mt)
        #pragma unroll
        for (int nt = 0; nt < 8; ++nt)
            #pragma unroll
            for (int i = 0; i < 4; ++i) acc[mt][nt][i] = 0;

    // ---- loader lambda (chunk c -> stage s) ----
    auto load_chunk = [&](int c, int s) {
        const uint32_t sa = sb + s * SM_STAGE + SM_A_OFF;
        const uint32_t sbB = sb + s * SM_STAGE + SM_B_OFF;
        #pragma unroll
        for (int i = 0; i < 2; ++i) {                 // A: 512 x 16B
            int id = tid + i * 256;
            int row = id >> 2, seg = id & 3;
            cp16(sa + row * STRIDE + seg * 16,
                 A + (size_t)(m0 + row) * INF + c * BK + seg * 16);
        }
        #pragma unroll
        for (int i = 0; i < 4; ++i) {                 // B: 1024 x 16B
            int id = tid + i * 256;
            int row = id >> 2, seg = id & 3;
            cp16(sbB + row * STRIDE + seg * 16,
                 B + (size_t)(n0 + row) * INF + c * BK + seg * 16);
        }
        cp_commit();
    };

    load_chunk(0, 0);

    for (int c = 0; c < KCHUNKS; ++c) {
        const int s = c & 1;
        if (c + 1 < KCHUNKS) { load_chunk(c + 1, s ^ 1); cp_wait1(); }
        else                 { cp_wait0(); }
        __syncthreads();

        const char* pA = smem + s * SM_STAGE + SM_A_OFF + (wm * 64 + rg) * STRIDE + tg * 4;
        const char* pB = smem + s * SM_STAGE + SM_B_OFF + (wn * 64 + rg) * STRIDE + tg * 4;

        #pragma unroll
        for (int ks = 0; ks < 2; ++ks) {
            const int koff = ks * 32;
            uint32_t a[4][4];
            #pragma unroll
            for (int mt = 0; mt < 4; ++mt) {
                a[mt][0] = *reinterpret_cast<const uint32_t*>(pA + (mt * 16    ) * STRIDE + koff);
                a[mt][1] = *reinterpret_cast<const uint32_t*>(pA + (mt * 16 + 8) * STRIDE + koff);
                a[mt][2] = *reinterpret_cast<const uint32_t*>(pA + (mt * 16    ) * STRIDE + koff + 16);
                a[mt][3] = *reinterpret_cast<const uint32_t*>(pA + (mt * 16 + 8) * STRIDE + koff + 16);
            }
            uint32_t b[8][2];
            #pragma unroll
            for (int nt = 0; nt < 8; ++nt) {
                b[nt][0] = *reinterpret_cast<const uint32_t*>(pB + nt * 8 * STRIDE + koff);
                b[nt][1] = *reinterpret_cast<const uint32_t*>(pB + nt * 8 * STRIDE + koff + 16);
            }
            #pragma unroll
            for (int mt = 0; mt < 4; ++mt)
                #pragma unroll
                for (int nt = 0; nt < 8; ++nt)
                    imma(acc[mt][nt], a[mt], b[nt]);
        }
        __syncthreads();
    }

    // ---- epilogue: s32 -> f32, float2 stores ----
    #pragma unroll
    for (int mt = 0; mt < 4; ++mt) {
        const int r0 = m0 + wm * 64 + mt * 16 + rg;
        #pragma unroll
        for (int nt = 0; nt < 8; ++nt) {
            const int cc = n0 + wn * 64 + nt * 8 + tg * 2;
            float2 v0 = make_float2((float)acc[mt][nt][0], (float)acc[mt][nt][1]);
            float2 v1 = make_float2((float)acc[mt][nt][2], (float)acc[mt][nt][3]);
            *reinterpret_cast<float2*>(&out[(size_t)r0 * OUTF + cc])       = v0;
            *reinterpret_cast<float2*>(&out[(size_t)(r0 + 8) * OUTF + cc]) = v1;
        }
    }
}

// ---------------------------------------------------------------------------
extern "C" void kernel_launch(void* const* d_in, const int* in_sizes, int n_in,
                              void* d_out, int out_size)
{
    const float* x = (const float*)d_in[0];
    const float* W = (const float*)d_in[1];
    if (n_in >= 2 && in_sizes[0] == OUTF * INF && in_sizes[1] == BATCH * INF) {
        x = (const float*)d_in[1];
        W = (const float*)d_in[0];
    }
    float* out = (float*)d_out;

    int8_t* X8; int8_t* W8;
    cudaGetSymbolAddress((void**)&X8, g_X8);
    cudaGetSymbolAddress((void**)&W8, g_W8);

    conv_x8_kernel<<<(int)((size_t)BATCH * INF / 16 / 256), 256>>>(x, X8);
    conv_w8_kernel<<<(int)((size_t)OUTF * INF / 16 / 256), 256>>>(W, W8);

    cudaFuncSetAttribute(bgemm_imma_kernel,
                         cudaFuncAttributeMaxDynamicSharedMemorySize, SM_TOTAL);
    dim3 grid(OUTF / BN, BATCH / BM);   // (16, 64)
    bgemm_imma_kernel<<<grid, 256, SM_TOTAL>>>(X8, W8, out);
}

// round 9
// speedup vs baseline: 1.9886x; 1.9886x over previous
#include <cuda_runtime.h>
#include <stdint.h>

// QLinearLayerSign, popc binary GEMM v2:
//   Xb[m] = bitmask(x[m,:] > 0), Wb[n] = bitmask(W[n,:] > 0), R[m] = popc(Xb[m,:])
//   out[m][n] = 2 * sum_w popc(Xb & Wb) - R[m]

#define BATCH 8192
#define INF   4096
#define OUTF  4096
#define KW    (INF / 32)        // 128 packed words per row

#define BM 128
#define BN 128
#define BKW 32                  // packed words per chunk (= 1024 original k)
#define KCHUNKS (KW / BKW)      // 4

#define STG_X  (BM * 128)       // 16 KB (128B per row, 32 words)
#define STG_SZ (STG_X + BN * 128)  // 32 KB per stage
#define SM_TOTAL (2 * STG_SZ)   // 64 KB

__device__ uint32_t g_Xb[(size_t)BATCH * KW];   // 4 MB
__device__ uint32_t g_Wb[(size_t)OUTF * KW];    // 2 MB
__device__ int      g_Xr[BATCH];

__device__ __forceinline__ uint32_t smem_u32(const void* p) {
    uint32_t a;
    asm("{ .reg .u64 t; cvta.to.shared.u64 t, %1; cvt.u32.u64 %0, t; }" : "=r"(a) : "l"(p));
    return a;
}
__device__ __forceinline__ void cp16(uint32_t dst, const void* src) {
    asm volatile("cp.async.cg.shared.global [%0], [%1], 16;" :: "r"(dst), "l"(src));
}
__device__ __forceinline__ void cp_commit() {
    asm volatile("cp.async.commit_group;" ::: "memory");
}
__device__ __forceinline__ void cp_wait1() { asm volatile("cp.async.wait_group 1;" ::: "memory"); }
__device__ __forceinline__ void cp_wait0() { asm volatile("cp.async.wait_group 0;" ::: "memory"); }

// ---------------------------------------------------------------------------
// Pack: warp packs 128 consecutive floats -> 4 words (uint4 store by lane 0).
// bit (e mod 32) of word (e/32) = (src[e] > 0).
// ---------------------------------------------------------------------------
__global__ __launch_bounds__(256) void pack_kernel(const float* __restrict__ src,
                                                   uint32_t* __restrict__ dst)
{
    const int gw   = (int)(blockIdx.x * 8 + (threadIdx.x >> 5));  // global warp id
    const int lane = threadIdx.x & 31;
    float4 f = *reinterpret_cast<const float4*>(src + (size_t)gw * 128 + lane * 4);
    uint32_t nib = (f.x > 0.f ? 1u : 0u) | (f.y > 0.f ? 2u : 0u) |
                   (f.z > 0.f ? 4u : 0u) | (f.w > 0.f ? 8u : 0u);
    uint32_t v = nib << ((lane & 7) * 4);
    v |= __shfl_xor_sync(0xFFFFFFFFu, v, 1);
    v |= __shfl_xor_sync(0xFFFFFFFFu, v, 2);
    v |= __shfl_xor_sync(0xFFFFFFFFu, v, 4);
    uint32_t w0 = __shfl_sync(0xFFFFFFFFu, v, 0);
    uint32_t w1 = __shfl_sync(0xFFFFFFFFu, v, 8);
    uint32_t w2 = __shfl_sync(0xFFFFFFFFu, v, 16);
    uint32_t w3 = __shfl_sync(0xFFFFFFFFu, v, 24);
    if (lane == 0)
        *reinterpret_cast<uint4*>(dst + (size_t)gw * 4) = make_uint4(w0, w1, w2, w3);
}

// ---------------------------------------------------------------------------
// Per-row popcount of packed X (one warp per row).
// ---------------------------------------------------------------------------
__global__ __launch_bounds__(256) void row_popc_kernel(
    const uint32_t* __restrict__ Xb, int* __restrict__ Xr, int rows)
{
    int row  = (int)(blockIdx.x * 8 + (threadIdx.x >> 5));
    int lane = threadIdx.x & 31;
    if (row >= rows) return;
    const uint32_t* p = Xb + (size_t)row * KW;
    int s = 0;
    #pragma unroll
    for (int i = 0; i < KW / 32; i++) s += __popc(p[lane + i * 32]);
    #pragma unroll
    for (int o = 16; o; o >>= 1) s += __shfl_xor_sync(0xFFFFFFFFu, s, o);
    if (lane == 0) Xr[row] = s;
}

// ---------------------------------------------------------------------------
// popc GEMM v2: CTA 128x128, 256 threads, 8x8 per thread, LDS.128 fragments,
// XOR-swizzled smem (conflict-free), 2-stage cp.async over 4 k-chunks.
// smem layout per tile: row r, 16B-segment s stored at r*128 + (s ^ (r>>3 & 7))*16.
// ---------------------------------------------------------------------------
__global__ __launch_bounds__(256, 2)
void bgemm_popc2_kernel(const uint32_t* __restrict__ Xb,
                        const uint32_t* __restrict__ Wb,
                        const int*      __restrict__ Xr,
                        float*          __restrict__ out)
{
    extern __shared__ char smem[];
    const uint32_t sb = smem_u32(smem);
    const int tid = threadIdx.x;
    const int tx  = tid & 15;          // -> n (8 cols each)
    const int ty  = tid >> 4;          // -> m (8 rows each)
    const int m0  = blockIdx.y * BM;
    const int n0  = blockIdx.x * BN;

    const int sA = ty & 7;             // swizzle key for a-rows (row>>3 == ty)
    const int sB = tx & 7;             // swizzle key for b-rows (row>>3 == tx)

    // loader: chunk c -> stage s. 1024 x 16B per tile, 4 per thread per tile.
    auto load_chunk = [&](int c, int s) {
        const uint32_t bx = sb + s * STG_SZ;
        const uint32_t bw = bx + STG_X;
        #pragma unroll
        for (int i = 0; i < 4; ++i) {
            int id  = i * 256 + tid;
            int row = id >> 3, seg = id & 7;
            int sw  = (seg ^ ((row >> 3) & 7)) * 16;
            cp16(bx + row * 128 + sw, Xb + (size_t)(m0 + row) * KW + c * BKW + seg * 4);
        }
        #pragma unroll
        for (int i = 0; i < 4; ++i) {
            int id  = i * 256 + tid;
            int row = id >> 3, seg = id & 7;
            int sw  = (seg ^ ((row >> 3) & 7)) * 16;
            cp16(bw + row * 128 + sw, Wb + (size_t)(n0 + row) * KW + c * BKW + seg * 4);
        }
        cp_commit();
    };

    int acc[8][8];
    #pragma unroll
    for (int i = 0; i < 8; ++i)
        #pragma unroll
        for (int j = 0; j < 8; ++j) acc[i][j] = 0;

    load_chunk(0, 0);

    for (int c = 0; c < KCHUNKS; ++c) {
        const int s = c & 1;
        if (c + 1 < KCHUNKS) { load_chunk(c + 1, s ^ 1); cp_wait1(); }
        else                 { cp_wait0(); }
        __syncthreads();

        const char* xs = smem + s * STG_SZ + (ty * 8) * 128;
        const char* ws = smem + s * STG_SZ + STG_X + (tx * 8) * 128;

        #pragma unroll
        for (int k4 = 0; k4 < 8; ++k4) {
            const int ca = (k4 ^ sA) * 16;
            const int cb = (k4 ^ sB) * 16;
            uint4 a[8];
            #pragma unroll
            for (int mt = 0; mt < 8; ++mt)
                a[mt] = *reinterpret_cast<const uint4*>(xs + mt * 128 + ca);
            #pragma unroll
            for (int nt = 0; nt < 8; ++nt) {
                uint4 b = *reinterpret_cast<const uint4*>(ws + nt * 128 + cb);
                #pragma unroll
                for (int mt = 0; mt < 8; ++mt) {
                    acc[mt][nt] += __popc(a[mt].x & b.x) + __popc(a[mt].y & b.y)
                                 + __popc(a[mt].z & b.z) + __popc(a[mt].w & b.w);
                }
            }
        }
        __syncthreads();
    }

    // Epilogue: out = 2*S - R[m]; two float4 stores per row.
    #pragma unroll
    for (int mt = 0; mt < 8; ++mt) {
        const int m = m0 + ty * 8 + mt;
        const int R = Xr[m];
        float* orow = out + (size_t)m * OUTF + n0 + tx * 8;
        float4 v0, v1;
        v0.x = (float)(2 * acc[mt][0] - R);
        v0.y = (float)(2 * acc[mt][1] - R);
        v0.z = (float)(2 * acc[mt][2] - R);
        v0.w = (float)(2 * acc[mt][3] - R);
        v1.x = (float)(2 * acc[mt][4] - R);
        v1.y = (float)(2 * acc[mt][5] - R);
        v1.z = (float)(2 * acc[mt][6] - R);
        v1.w = (float)(2 * acc[mt][7] - R);
        *reinterpret_cast<float4*>(orow)     = v0;
        *reinterpret_cast<float4*>(orow + 4) = v1;
    }
}

// ---------------------------------------------------------------------------
extern "C" void kernel_launch(void* const* d_in, const int* in_sizes, int n_in,
                              void* d_out, int out_size)
{
    const float* x = (const float*)d_in[0];
    const float* W = (const float*)d_in[1];
    if (n_in >= 2 && in_sizes[0] == OUTF * INF && in_sizes[1] == BATCH * INF) {
        x = (const float*)d_in[1];
        W = (const float*)d_in[0];
    }
    float* out = (float*)d_out;

    uint32_t* Xb; uint32_t* Wb; int* Xr;
    cudaGetSymbolAddress((void**)&Xb, g_Xb);
    cudaGetSymbolAddress((void**)&Wb, g_Wb);
    cudaGetSymbolAddress((void**)&Xr, g_Xr);

    // Pack (warp = 128 floats): X -> 32768 blocks, W -> 16384 blocks.
    pack_kernel<<<(int)((size_t)BATCH * INF / 128 / 8), 256>>>(x, Xb);
    pack_kernel<<<(int)((size_t)OUTF * INF / 128 / 8), 256>>>(W, Wb);
    row_popc_kernel<<<BATCH / 8, 256>>>(Xb, Xr, BATCH);

    cudaFuncSetAttribute(bgemm_popc2_kernel,
                         cudaFuncAttributeMaxDynamicSharedMemorySize, SM_TOTAL);
    dim3 grid(OUTF / BN, BATCH / BM);   // (32, 64)
    bgemm_popc2_kernel<<<grid, 256, SM_TOTAL>>>(Xb, Wb, Xr, out);
}

// round 10
// speedup vs baseline: 2.2054x; 1.1090x over previous
#include <cuda_runtime.h>
#include <stdint.h>

// QLinearLayerSign, popc binary GEMM v3:
//   Xb[m] = bitmask(x[m,:] > 0), Wb[n] = bitmask(W[n,:] > 0), R[m] = popc(Xb[m,:])
//   out[m][n] = 2 * sum_w popc(Xb & Wb) - R[m]
// v3: CTA 64x64, 4x4 thread tile, uint4 fragments, occupancy-first (4 CTA/SM).

#define BATCH 8192
#define INF   4096
#define OUTF  4096
#define KW    (INF / 32)        // 128 packed words per row

#define BM 64
#define BN 64
#define BKW 32                  // packed words per chunk (128B per row)
#define KCHUNKS (KW / BKW)      // 4

#define STG_X  (BM * 128)          // 8 KB
#define STG_SZ (STG_X + BN * 128)  // 16 KB per stage
#define SM_TOTAL (2 * STG_SZ)      // 32 KB

__device__ uint32_t g_Xb[(size_t)BATCH * KW];   // 4 MB
__device__ uint32_t g_Wb[(size_t)OUTF * KW];    // 2 MB
__device__ int      g_Xr[BATCH];

__device__ __forceinline__ uint32_t smem_u32(const void* p) {
    uint32_t a;
    asm("{ .reg .u64 t; cvta.to.shared.u64 t, %1; cvt.u32.u64 %0, t; }" : "=r"(a) : "l"(p));
    return a;
}
__device__ __forceinline__ void cp16(uint32_t dst, const void* src) {
    asm volatile("cp.async.cg.shared.global [%0], [%1], 16;" :: "r"(dst), "l"(src));
}
__device__ __forceinline__ void cp_commit() {
    asm volatile("cp.async.commit_group;" ::: "memory");
}
__device__ __forceinline__ void cp_wait1() { asm volatile("cp.async.wait_group 1;" ::: "memory"); }
__device__ __forceinline__ void cp_wait0() { asm volatile("cp.async.wait_group 0;" ::: "memory"); }

// ---------------------------------------------------------------------------
// Pack: warp packs 128 consecutive floats -> 4 words (uint4 store by lane 0).
// ---------------------------------------------------------------------------
__global__ __launch_bounds__(256) void pack_kernel(const float* __restrict__ src,
                                                   uint32_t* __restrict__ dst)
{
    const int gw   = (int)(blockIdx.x * 8 + (threadIdx.x >> 5));
    const int lane = threadIdx.x & 31;
    float4 f = *reinterpret_cast<const float4*>(src + (size_t)gw * 128 + lane * 4);
    uint32_t nib = (f.x > 0.f ? 1u : 0u) | (f.y > 0.f ? 2u : 0u) |
                   (f.z > 0.f ? 4u : 0u) | (f.w > 0.f ? 8u : 0u);
    uint32_t v = nib << ((lane & 7) * 4);
    v |= __shfl_xor_sync(0xFFFFFFFFu, v, 1);
    v |= __shfl_xor_sync(0xFFFFFFFFu, v, 2);
    v |= __shfl_xor_sync(0xFFFFFFFFu, v, 4);
    uint32_t w0 = __shfl_sync(0xFFFFFFFFu, v, 0);
    uint32_t w1 = __shfl_sync(0xFFFFFFFFu, v, 8);
    uint32_t w2 = __shfl_sync(0xFFFFFFFFu, v, 16);
    uint32_t w3 = __shfl_sync(0xFFFFFFFFu, v, 24);
    if (lane == 0)
        *reinterpret_cast<uint4*>(dst + (size_t)gw * 4) = make_uint4(w0, w1, w2, w3);
}

// ---------------------------------------------------------------------------
__global__ __launch_bounds__(256) void row_popc_kernel(
    const uint32_t* __restrict__ Xb, int* __restrict__ Xr, int rows)
{
    int row  = (int)(blockIdx.x * 8 + (threadIdx.x >> 5));
    int lane = threadIdx.x & 31;
    if (row >= rows) return;
    const uint32_t* p = Xb + (size_t)row * KW;
    int s = 0;
    #pragma unroll
    for (int i = 0; i < KW / 32; i++) s += __popc(p[lane + i * 32]);
    #pragma unroll
    for (int o = 16; o; o >>= 1) s += __shfl_xor_sync(0xFFFFFFFFu, s, o);
    if (lane == 0) Xr[row] = s;
}

// ---------------------------------------------------------------------------
// popc GEMM v3: CTA 64x64 (256 threads, 4x4/thread), uint4 fragments,
// XOR-swizzled smem, 2-stage cp.async, 4 CTAs/SM.
// smem: row r, 16B-seg s at r*128 + (s ^ ((r>>3)&7))*16.
// ---------------------------------------------------------------------------
__global__ __launch_bounds__(256, 4)
void bgemm_popc3_kernel(const uint32_t* __restrict__ Xb,
                        const uint32_t* __restrict__ Wb,
                        const int*      __restrict__ Xr,
                        float*          __restrict__ out)
{
    extern __shared__ char smem[];
    const uint32_t sb = smem_u32(smem);
    const int tid = threadIdx.x;
    const int tx  = tid & 15;          // -> n (4 cols each)
    const int ty  = tid >> 4;          // -> m (4 rows each)
    const int m0  = blockIdx.y * BM;
    const int n0  = blockIdx.x * BN;

    const int sA = (ty >> 1) & 7;      // (row>>3)&7 for rows ty*4..ty*4+3
    const int sB = (tx >> 1) & 7;

    // loader: chunk c -> stage s. 512 x 16B per tile, 2 per thread per tile.
    auto load_chunk = [&](int c, int s) {
        const uint32_t bx = sb + s * STG_SZ;
        const uint32_t bw = bx + STG_X;
        #pragma unroll
        for (int i = 0; i < 2; ++i) {
            int id  = i * 256 + tid;
            int row = id >> 3, seg = id & 7;
            int sw  = (seg ^ ((row >> 3) & 7)) * 16;
            cp16(bx + row * 128 + sw, Xb + (size_t)(m0 + row) * KW + c * BKW + seg * 4);
        }
        #pragma unroll
        for (int i = 0; i < 2; ++i) {
            int id  = i * 256 + tid;
            int row = id >> 3, seg = id & 7;
            int sw  = (seg ^ ((row >> 3) & 7)) * 16;
            cp16(bw + row * 128 + sw, Wb + (size_t)(n0 + row) * KW + c * BKW + seg * 4);
        }
        cp_commit();
    };

    int acc[4][4];
    #pragma unroll
    for (int i = 0; i < 4; ++i)
        #pragma unroll
        for (int j = 0; j < 4; ++j) acc[i][j] = 0;

    load_chunk(0, 0);

    for (int c = 0; c < KCHUNKS; ++c) {
        const int s = c & 1;
        if (c + 1 < KCHUNKS) { load_chunk(c + 1, s ^ 1); cp_wait1(); }
        else                 { cp_wait0(); }
        __syncthreads();

        const char* xs = smem + s * STG_SZ + (ty * 4) * 128;
        const char* ws = smem + s * STG_SZ + STG_X + (tx * 4) * 128;

        #pragma unroll
        for (int k4 = 0; k4 < 8; ++k4) {
            const int ca = (k4 ^ sA) * 16;
            const int cb = (k4 ^ sB) * 16;
            uint4 a0 = *reinterpret_cast<const uint4*>(xs + 0 * 128 + ca);
            uint4 a1 = *reinterpret_cast<const uint4*>(xs + 1 * 128 + ca);
            uint4 a2 = *reinterpret_cast<const uint4*>(xs + 2 * 128 + ca);
            uint4 a3 = *reinterpret_cast<const uint4*>(xs + 3 * 128 + ca);
            #pragma unroll
            for (int nt = 0; nt < 4; ++nt) {
                uint4 b = *reinterpret_cast<const uint4*>(ws + nt * 128 + cb);
                acc[0][nt] += __popc(a0.x & b.x) + __popc(a0.y & b.y)
                            + __popc(a0.z & b.z) + __popc(a0.w & b.w);
                acc[1][nt] += __popc(a1.x & b.x) + __popc(a1.y & b.y)
                            + __popc(a1.z & b.z) + __popc(a1.w & b.w);
                acc[2][nt] += __popc(a2.x & b.x) + __popc(a2.y & b.y)
                            + __popc(a2.z & b.z) + __popc(a2.w & b.w);
                acc[3][nt] += __popc(a3.x & b.x) + __popc(a3.y & b.y)
                            + __popc(a3.z & b.z) + __popc(a3.w & b.w);
            }
        }
        __syncthreads();
    }

    // Epilogue: out = 2*S - R[m]; one float4 store per row.
    #pragma unroll
    for (int mt = 0; mt < 4; ++mt) {
        const int m = m0 + ty * 4 + mt;
        const int R = Xr[m];
        float4 v;
        v.x = (float)(2 * acc[mt][0] - R);
        v.y = (float)(2 * acc[mt][1] - R);
        v.z = (float)(2 * acc[mt][2] - R);
        v.w = (float)(2 * acc[mt][3] - R);
        *reinterpret_cast<float4*>(&out[(size_t)m * OUTF + n0 + tx * 4]) = v;
    }
}

// ---------------------------------------------------------------------------
extern "C" void kernel_launch(void* const* d_in, const int* in_sizes, int n_in,
                              void* d_out, int out_size)
{
    const float* x = (const float*)d_in[0];
    const float* W = (const float*)d_in[1];
    if (n_in >= 2 && in_sizes[0] == OUTF * INF && in_sizes[1] == BATCH * INF) {
        x = (const float*)d_in[1];
        W = (const float*)d_in[0];
    }
    float* out = (float*)d_out;

    uint32_t* Xb; uint32_t* Wb; int* Xr;
    cudaGetSymbolAddress((void**)&Xb, g_Xb);
    cudaGetSymbolAddress((void**)&Wb, g_Wb);
    cudaGetSymbolAddress((void**)&Xr, g_Xr);

    pack_kernel<<<(int)((size_t)BATCH * INF / 128 / 8), 256>>>(x, Xb);
    pack_kernel<<<(int)((size_t)OUTF * INF / 128 / 8), 256>>>(W, Wb);
    row_popc_kernel<<<BATCH / 8, 256>>>(Xb, Xr, BATCH);

    cudaFuncSetAttribute(bgemm_popc3_kernel,
                         cudaFuncAttributeMaxDynamicSharedMemorySize, SM_TOTAL);
    dim3 grid(OUTF / BN, BATCH / BM);   // (64, 128)
    bgemm_popc3_kernel<<<grid, 256, SM_TOTAL>>>(Xb, Wb, Xr, out);
}